// round 1
// baseline (speedup 1.0000x reference)
#include <cuda_runtime.h>

// Problem constants
#define BB 4
#define SS 2048
#define DD 1024
#define HH 16
#define DHH 64
#define MTOT (BB*SS)     // 8192
#define NTOT (3*DD)      // 3072
#define KTOT (DD)        // 1024

// Scratch: Q/K/V in [B,H,S,DH] layout (attention-friendly)
__device__ float g_Q[(size_t)BB*HH*SS*DHH];
__device__ float g_K[(size_t)BB*HH*SS*DHH];
__device__ float g_V[(size_t)BB*HH*SS*DHH];

// ---------------------------------------------------------------------------
// Kernel 1: QKV GEMM  out[m,n] = x[m,:] @ W[:,n] + bias[n], scattered to Q/K/V
// Tile: BM=128, BN=64, BK=16, 256 threads, 8x4 microtile per thread.
// ---------------------------------------------------------------------------
#define GBM 128
#define GBN 64
#define GBK 16

__global__ __launch_bounds__(256) void qkv_gemm_kernel(
    const float* __restrict__ x,
    const float* __restrict__ W,
    const float* __restrict__ bias)
{
    __shared__ float As[GBK][GBM];   // transposed A tile
    __shared__ float Bs[GBK][GBN];

    const int t  = threadIdx.x;
    const int m0 = blockIdx.y * GBM;
    const int n0 = blockIdx.x * GBN;
    const int ty = t / 16;           // 0..15 -> rows ty*8 .. ty*8+7
    const int tx = t % 16;           // 0..15 -> cols tx*4 .. tx*4+3

    // loader mapping
    const int arow = t / 4;          // 0..63 (and +64)
    const int acol = (t % 4) * 4;    // 0,4,8,12
    const int brow = t / 16;         // 0..15
    const int bcol = (t % 16) * 4;   // 0..60

    float acc[8][4];
    #pragma unroll
    for (int i = 0; i < 8; i++)
        #pragma unroll
        for (int j = 0; j < 4; j++) acc[i][j] = 0.0f;

    for (int k0 = 0; k0 < KTOT; k0 += GBK) {
        float4 a0 = *(const float4*)&x[(size_t)(m0 + arow     ) * KTOT + k0 + acol];
        float4 a1 = *(const float4*)&x[(size_t)(m0 + arow + 64) * KTOT + k0 + acol];
        float4 b0 = *(const float4*)&W[(size_t)(k0 + brow) * NTOT + n0 + bcol];

        As[acol + 0][arow] = a0.x;  As[acol + 1][arow] = a0.y;
        As[acol + 2][arow] = a0.z;  As[acol + 3][arow] = a0.w;
        As[acol + 0][arow + 64] = a1.x;  As[acol + 1][arow + 64] = a1.y;
        As[acol + 2][arow + 64] = a1.z;  As[acol + 3][arow + 64] = a1.w;
        *(float4*)&Bs[brow][bcol] = b0;
        __syncthreads();

        #pragma unroll
        for (int k = 0; k < GBK; k++) {
            float4 av0 = *(const float4*)&As[k][ty * 8];
            float4 av1 = *(const float4*)&As[k][ty * 8 + 4];
            float4 bv  = *(const float4*)&Bs[k][tx * 4];
            float a[8] = {av0.x, av0.y, av0.z, av0.w, av1.x, av1.y, av1.z, av1.w};
            float b[4] = {bv.x, bv.y, bv.z, bv.w};
            #pragma unroll
            for (int i = 0; i < 8; i++)
                #pragma unroll
                for (int j = 0; j < 4; j++)
                    acc[i][j] += a[i] * b[j];
        }
        __syncthreads();
    }

    // Epilogue: add bias, scatter into Q/K/V [B,H,S,DH]
    // n decomposition per reference: h = n/(3*DH), which = (n/DH)%3, dh = n%DH
    #pragma unroll
    for (int i = 0; i < 8; i++) {
        const int m = m0 + ty * 8 + i;
        const int bidx = m / SS;
        const int sidx = m % SS;
        #pragma unroll
        for (int j = 0; j < 4; j++) {
            const int n = n0 + tx * 4 + j;
            const float v = acc[i][j] + bias[n];
            const int h     = n / (3 * DHH);
            const int which = (n / DHH) % 3;
            const int dh    = n % DHH;
            float* dst = (which == 0) ? g_Q : (which == 1 ? g_K : g_V);
            dst[(size_t)((bidx * HH + h) * SS + sidx) * DHH + dh] = v;
        }
    }
}

// ---------------------------------------------------------------------------
// Kernel 2: causal flash attention, fp32.
// One query row per thread; 128 query rows per block; K/V tiles of 64 in smem.
// grid = (S/128, B*H)
// ---------------------------------------------------------------------------
#define ATT_QROWS 128
#define ATT_KTILE 64

__global__ __launch_bounds__(128) void attn_kernel(float* __restrict__ out)
{
    __shared__ float Ks[ATT_KTILE * DHH];
    __shared__ float Vs[ATT_KTILE * DHH];

    const int bh  = blockIdx.y;           // 0..63
    const int qt  = blockIdx.x;           // 0..15
    const int tid = threadIdx.x;          // 0..127
    const int qi  = qt * ATT_QROWS + tid; // global query row within S

    // Load this thread's query row into registers
    const float* Qbase = g_Q + (size_t)(bh * SS + qi) * DHH;
    float4 q4[16];
    #pragma unroll
    for (int d = 0; d < 16; d++) q4[d] = ((const float4*)Qbase)[d];

    float4 o4[16];
    #pragma unroll
    for (int d = 0; d < 16; d++) o4[d] = make_float4(0.f, 0.f, 0.f, 0.f);

    float m = -1e30f;
    float l = 0.0f;

    const int qmax   = qt * ATT_QROWS + (ATT_QROWS - 1);
    const int ntiles = qmax / ATT_KTILE + 1;   // causal: only tiles that intersect

    for (int jt = 0; jt < ntiles; jt++) {
        const int j0 = jt * ATT_KTILE;
        const float* Kg = g_K + (size_t)(bh * SS + j0) * DHH;
        const float* Vg = g_V + (size_t)(bh * SS + j0) * DHH;

        __syncthreads();   // protect previous tile's smem use
        #pragma unroll
        for (int i = 0; i < 8; i++) {
            ((float4*)Ks)[tid + i * 128] = ((const float4*)Kg)[tid + i * 128];
            ((float4*)Vs)[tid + i * 128] = ((const float4*)Vg)[tid + i * 128];
        }
        __syncthreads();

        const bool full = (j0 + ATT_KTILE - 1) <= qi;   // whole tile unmasked

        #pragma unroll 1
        for (int cc = 0; cc < 4; cc++) {
            float sv[16];
            float chmax = -1e30f;

            // --- scores: s = (q . k) / sqrt(DH) ---
            #pragma unroll
            for (int u = 0; u < 16; u++) {
                const int kk = cc * 16 + u;
                const float4* Kr = (const float4*)(Ks + kk * DHH);
                float sA = 0.f, sB = 0.f;
                #pragma unroll
                for (int d = 0; d < 16; d += 2) {
                    float4 kv0 = Kr[d];
                    float4 kv1 = Kr[d + 1];
                    sA += q4[d].x * kv0.x + q4[d].y * kv0.y
                        + q4[d].z * kv0.z + q4[d].w * kv0.w;
                    sB += q4[d+1].x * kv1.x + q4[d+1].y * kv1.y
                        + q4[d+1].z * kv1.z + q4[d+1].w * kv1.w;
                }
                float ss = (sA + sB) * 0.125f;
                if (!full && (j0 + kk) > qi) ss = -1e30f;
                sv[u] = ss;
                chmax = fmaxf(chmax, ss);
            }

            // --- online softmax update ---
            const float m_new = fmaxf(m, chmax);
            const float scale = __expf(m - m_new);
            m = m_new;
            l *= scale;
            #pragma unroll
            for (int d = 0; d < 16; d++) {
                o4[d].x *= scale; o4[d].y *= scale;
                o4[d].z *= scale; o4[d].w *= scale;
            }

            // --- accumulate p @ V ---
            #pragma unroll
            for (int u = 0; u < 16; u++) {
                const int kk = cc * 16 + u;
                const float p = __expf(sv[u] - m);
                l += p;
                const float4* Vr = (const float4*)(Vs + kk * DHH);
                #pragma unroll
                for (int d = 0; d < 16; d++) {
                    float4 vv = Vr[d];
                    o4[d].x += p * vv.x; o4[d].y += p * vv.y;
                    o4[d].z += p * vv.z; o4[d].w += p * vv.w;
                }
            }
        }
    }

    // Write context back: out[b, qi, h*DH + d]
    const float inv = 1.0f / l;
    const int b = bh / HH;
    const int h = bh % HH;
    float* obase = out + (size_t)(b * SS + qi) * DD + h * DHH;
    #pragma unroll
    for (int d = 0; d < 16; d++) {
        float4 vv = o4[d];
        vv.x *= inv; vv.y *= inv; vv.z *= inv; vv.w *= inv;
        ((float4*)obase)[d] = vv;
    }
}

// ---------------------------------------------------------------------------
extern "C" void kernel_launch(void* const* d_in, const int* in_sizes, int n_in,
                              void* d_out, int out_size)
{
    const float* x    = (const float*)d_in[0];   // [B,S,D]
    const float* W    = (const float*)d_in[1];   // [D,3D]
    const float* bias = (const float*)d_in[2];   // [3D]
    float* out        = (float*)d_out;           // [B,S,D]

    dim3 gemm_grid(NTOT / GBN, MTOT / GBM);      // (48, 64)
    qkv_gemm_kernel<<<gemm_grid, 256>>>(x, W, bias);

    dim3 attn_grid(SS / ATT_QROWS, BB * HH);     // (16, 64)
    attn_kernel<<<attn_grid, 128>>>(out);
}

// round 3
// speedup vs baseline: 1.2342x; 1.2342x over previous
#include <cuda_runtime.h>
#include <cuda_bf16.h>
#include <cstdint>

// Problem constants
#define BB 4
#define SS 2048
#define DD 1024
#define HH 16
#define DHH 64
#define MTOT (BB*SS)     // 8192
#define NTOT (3*DD)      // 3072
#define KTOT (DD)        // 1024
#define KP   (3*KTOT)    // 3072: expanded K -> [hi|hi|lo] x [hi|lo|hi]

// Scratch
__device__ __align__(16) float g_Q[(size_t)BB*HH*SS*DHH];
__device__ __align__(16) float g_K[(size_t)BB*HH*SS*DHH];
__device__ __align__(16) float g_V[(size_t)BB*HH*SS*DHH];
__device__ __align__(16) __nv_bfloat16 g_A[(size_t)MTOT*KP];   // [M, K'] K-major
__device__ __align__(16) __nv_bfloat16 g_B[(size_t)NTOT*KP];   // [N, K'] K-major

// ---------------------------------------------------------------------------
// Helpers (sm_103 baseline-safe: ldmatrix / mma.sync / cp.async only)
// ---------------------------------------------------------------------------
__device__ __forceinline__ uint32_t smem_u32(const void* p) {
    uint32_t a;
    asm("{ .reg .u64 t; cvta.to.shared.u64 t, %1; cvt.u32.u64 %0, t; }" : "=r"(a) : "l"(p));
    return a;
}
__device__ __forceinline__ void ldm_x4(uint32_t* r, uint32_t addr) {
    asm volatile("ldmatrix.sync.aligned.m8n8.x4.shared.b16 {%0,%1,%2,%3}, [%4];"
        : "=r"(r[0]), "=r"(r[1]), "=r"(r[2]), "=r"(r[3]) : "r"(addr));
}
__device__ __forceinline__ void mma16816(float* d, const uint32_t* a, uint32_t b0, uint32_t b1) {
    asm volatile("mma.sync.aligned.m16n8k16.row.col.f32.bf16.bf16.f32 "
        "{%0,%1,%2,%3}, {%4,%5,%6,%7}, {%8,%9}, {%0,%1,%2,%3};"
        : "+f"(d[0]), "+f"(d[1]), "+f"(d[2]), "+f"(d[3])
        : "r"(a[0]), "r"(a[1]), "r"(a[2]), "r"(a[3]), "r"(b0), "r"(b1));
}
__device__ __forceinline__ void cp16(uint32_t dst, const void* src) {
    asm volatile("cp.async.cg.shared.global [%0], [%1], 16;" :: "r"(dst), "l"(src));
}
#define CP_COMMIT() asm volatile("cp.async.commit_group;" ::: "memory")
#define CP_WAIT1()  asm volatile("cp.async.wait_group 1;" ::: "memory")

// ---------------------------------------------------------------------------
// Conversion: x -> bf16 hi/lo expanded A' [M, 3K]; sectors [hi | hi | lo]
// ---------------------------------------------------------------------------
__global__ __launch_bounds__(256) void conv_x_kernel(const float* __restrict__ x)
{
    const int idx  = blockIdx.x * 256 + threadIdx.x;
    const int base = idx * 4;
    const int m = base >> 10;
    const int k = base & 1023;
    float4 v = *(const float4*)(x + base);

    __nv_bfloat16 h0 = __float2bfloat16(v.x);
    __nv_bfloat16 h1 = __float2bfloat16(v.y);
    __nv_bfloat16 h2 = __float2bfloat16(v.z);
    __nv_bfloat16 h3 = __float2bfloat16(v.w);
    __nv_bfloat16 l0 = __float2bfloat16(v.x - __bfloat162float(h0));
    __nv_bfloat16 l1 = __float2bfloat16(v.y - __bfloat162float(h1));
    __nv_bfloat16 l2 = __float2bfloat16(v.z - __bfloat162float(h2));
    __nv_bfloat16 l3 = __float2bfloat16(v.w - __bfloat162float(h3));

    __nv_bfloat162 ha; ha.x = h0; ha.y = h1;
    __nv_bfloat162 hb; hb.x = h2; hb.y = h3;
    __nv_bfloat162 la; la.x = l0; la.y = l1;
    __nv_bfloat162 lb; lb.x = l2; lb.y = l3;

    __nv_bfloat16* row = g_A + (size_t)m * KP;
    *(__nv_bfloat162*)(row + k)          = ha;
    *(__nv_bfloat162*)(row + k + 2)      = hb;
    *(__nv_bfloat162*)(row + k + 1024)   = ha;
    *(__nv_bfloat162*)(row + k + 1026)   = hb;
    *(__nv_bfloat162*)(row + k + 2048)   = la;
    *(__nv_bfloat162*)(row + k + 2050)   = lb;
}

// ---------------------------------------------------------------------------
// Conversion: W [K,N] -> B' [N, 3K] bf16, sectors [hi | lo | hi] (transpose)
// ---------------------------------------------------------------------------
__global__ __launch_bounds__(256) void conv_w_kernel(const float* __restrict__ W)
{
    __shared__ float T[32][33];
    const int n0 = blockIdx.x * 32;
    const int k0 = blockIdx.y * 32;
    const int tx = threadIdx.x;   // 0..31
    const int ty = threadIdx.y;   // 0..7

    #pragma unroll
    for (int i = 0; i < 4; i++)
        T[ty + i * 8][tx] = W[(size_t)(k0 + ty + i * 8) * NTOT + n0 + tx];
    __syncthreads();

    #pragma unroll
    for (int i = 0; i < 4; i++) {
        const int n = n0 + ty + i * 8;
        const float v = T[tx][ty + i * 8];
        __nv_bfloat16 hi = __float2bfloat16(v);
        __nv_bfloat16 lo = __float2bfloat16(v - __bfloat162float(hi));
        __nv_bfloat16* row = g_B + (size_t)n * KP;
        row[k0 + tx]        = hi;
        row[k0 + tx + 1024] = lo;
        row[k0 + tx + 2048] = hi;
    }
}

// ---------------------------------------------------------------------------
// HMMA GEMM: C[8192,3072] = A'[8192,3072] @ B'[3072,3072]^T (both K-major bf16)
// CTA tile 128x128, BK=32, 3-stage cp.async pipeline, 8 warps (2m x 4n), warp
// tile 64x32 via m16n8k16. SMEM rows padded to 80B -> conflict-free ldmatrix.
// Epilogue: +bias, scatter to Q/K/V [B,H,S,DH].
// ---------------------------------------------------------------------------
#define ROWB 80
#define STG_BYTES (128*ROWB*2)   // A(10240) + B(10240) = 20480 per stage
#define GSTG 3
#define GEMM_SMEM (GSTG*STG_BYTES)  // 61440

__device__ __forceinline__ void gemm_load_stage(uint32_t smb, int s, int kc,
                                                int m0, int n0, int tid)
{
    const int row = tid >> 1;
    const int c0  = (tid & 1) * 2;    // chunk 0/2 -> covers 32B
    const __nv_bfloat16* asrc = g_A + (size_t)(m0 + row) * KP + kc + c0 * 8;
    uint32_t adst = smb + s * STG_BYTES + row * ROWB + c0 * 16;
    cp16(adst,      asrc);
    cp16(adst + 16, asrc + 8);
    const __nv_bfloat16* bsrc = g_B + (size_t)(n0 + row) * KP + kc + c0 * 8;
    uint32_t bdst = smb + s * STG_BYTES + 128 * ROWB + row * ROWB + c0 * 16;
    cp16(bdst,      bsrc);
    cp16(bdst + 16, bsrc + 8);
}

__global__ __launch_bounds__(256, 2) void qkv_gemm_hmma(const float* __restrict__ bias)
{
    extern __shared__ __align__(16) char sm[];
    const uint32_t smb = smem_u32(sm);
    const int tid = threadIdx.x, lane = tid & 31, wid = tid >> 5;
    const int m0 = blockIdx.y * 128;
    const int n0 = blockIdx.x * 128;
    const int wm = wid & 1;        // 0..1 (64-row groups)
    const int wn = wid >> 1;       // 0..3 (32-col groups)

    float acc[4][4][4];
    #pragma unroll
    for (int i = 0; i < 4; i++)
        #pragma unroll
        for (int j = 0; j < 4; j++)
            #pragma unroll
            for (int r = 0; r < 4; r++) acc[i][j][r] = 0.0f;

    gemm_load_stage(smb, 0, 0,  m0, n0, tid);
    CP_COMMIT();
    gemm_load_stage(smb, 1, 32, m0, n0, tid);
    CP_COMMIT();

    const int NIT = KP / 32;   // 96
    for (int it = 0; it < NIT; it++) {
        CP_WAIT1();
        __syncthreads();
        if (it + 2 < NIT)
            gemm_load_stage(smb, (it + 2) % GSTG, (it + 2) * 32, m0, n0, tid);
        CP_COMMIT();

        const uint32_t sb = smb + (it % GSTG) * STG_BYTES;
        #pragma unroll
        for (int ks = 0; ks < 2; ks++) {
            uint32_t a[4][4], b[2][4];
            #pragma unroll
            for (int mt = 0; mt < 4; mt++) {
                const int r = wm * 64 + mt * 16 + (lane & 15);
                ldm_x4(a[mt], sb + r * ROWB + (ks * 2 + (lane >> 4)) * 16);
            }
            #pragma unroll
            for (int bt = 0; bt < 2; bt++) {
                const int r = wn * 32 + bt * 16 + (lane & 15);
                ldm_x4(b[bt], sb + 128 * ROWB + r * ROWB + (ks * 2 + (lane >> 4)) * 16);
            }
            #pragma unroll
            for (int mt = 0; mt < 4; mt++)
                #pragma unroll
                for (int nt = 0; nt < 4; nt++) {
                    const int bt = nt >> 1, sub = nt & 1;
                    mma16816(acc[mt][nt], a[mt], b[bt][sub], b[bt][sub + 2]);
                }
        }
    }

    // Epilogue: add bias, scatter into Q/K/V [B,H,S,DH]
    #pragma unroll
    for (int mt = 0; mt < 4; mt++) {
        #pragma unroll
        for (int nt = 0; nt < 4; nt++) {
            const int m = m0 + wm * 64 + mt * 16 + (lane >> 2);
            const int n = n0 + wn * 32 + (nt >> 1) * 16 + (nt & 1) * 8 + 2 * (lane & 3);
            const float2 bb = *(const float2*)(bias + n);
            const int h     = n / 192;
            const int which = (n >> 6) % 3;
            const int dh    = n & 63;
            float* dst = (which == 0) ? g_Q : (which == 1 ? g_K : g_V);
            const int bidx = m >> 11;
            const int sidx = m & 2047;
            float2 v0; v0.x = acc[mt][nt][0] + bb.x; v0.y = acc[mt][nt][1] + bb.y;
            *(float2*)(dst + ((size_t)((bidx * HH + h) * SS + sidx)) * DHH + dh) = v0;
            float2 v1; v1.x = acc[mt][nt][2] + bb.x; v1.y = acc[mt][nt][3] + bb.y;
            *(float2*)(dst + ((size_t)((bidx * HH + h) * SS + sidx + 8)) * DHH + dh) = v1;
        }
    }
}

// ---------------------------------------------------------------------------
// Kernel 2: causal flash attention, fp32 (unchanged from R1)
// ---------------------------------------------------------------------------
#define ATT_QROWS 128
#define ATT_KTILE 64

__global__ __launch_bounds__(128) void attn_kernel(float* __restrict__ out)
{
    __shared__ float Ks[ATT_KTILE * DHH];
    __shared__ float Vs[ATT_KTILE * DHH];

    const int bh  = blockIdx.y;
    const int qt  = blockIdx.x;
    const int tid = threadIdx.x;
    const int qi  = qt * ATT_QROWS + tid;

    const float* Qbase = g_Q + (size_t)(bh * SS + qi) * DHH;
    float4 q4[16];
    #pragma unroll
    for (int d = 0; d < 16; d++) q4[d] = ((const float4*)Qbase)[d];

    float4 o4[16];
    #pragma unroll
    for (int d = 0; d < 16; d++) o4[d] = make_float4(0.f, 0.f, 0.f, 0.f);

    float m = -1e30f;
    float l = 0.0f;

    const int qmax   = qt * ATT_QROWS + (ATT_QROWS - 1);
    const int ntiles = qmax / ATT_KTILE + 1;

    for (int jt = 0; jt < ntiles; jt++) {
        const int j0 = jt * ATT_KTILE;
        const float* Kg = g_K + (size_t)(bh * SS + j0) * DHH;
        const float* Vg = g_V + (size_t)(bh * SS + j0) * DHH;

        __syncthreads();
        #pragma unroll
        for (int i = 0; i < 8; i++) {
            ((float4*)Ks)[tid + i * 128] = ((const float4*)Kg)[tid + i * 128];
            ((float4*)Vs)[tid + i * 128] = ((const float4*)Vg)[tid + i * 128];
        }
        __syncthreads();

        const bool full = (j0 + ATT_KTILE - 1) <= qi;

        #pragma unroll 1
        for (int cc = 0; cc < 4; cc++) {
            float sv[16];
            float chmax = -1e30f;

            #pragma unroll
            for (int u = 0; u < 16; u++) {
                const int kk = cc * 16 + u;
                const float4* Kr = (const float4*)(Ks + kk * DHH);
                float sA = 0.f, sB = 0.f;
                #pragma unroll
                for (int d = 0; d < 16; d += 2) {
                    float4 kv0 = Kr[d];
                    float4 kv1 = Kr[d + 1];
                    sA += q4[d].x * kv0.x + q4[d].y * kv0.y
                        + q4[d].z * kv0.z + q4[d].w * kv0.w;
                    sB += q4[d+1].x * kv1.x + q4[d+1].y * kv1.y
                        + q4[d+1].z * kv1.z + q4[d+1].w * kv1.w;
                }
                float ss = (sA + sB) * 0.125f;
                if (!full && (j0 + kk) > qi) ss = -1e30f;
                sv[u] = ss;
                chmax = fmaxf(chmax, ss);
            }

            const float m_new = fmaxf(m, chmax);
            const float scale = __expf(m - m_new);
            m = m_new;
            l *= scale;
            #pragma unroll
            for (int d = 0; d < 16; d++) {
                o4[d].x *= scale; o4[d].y *= scale;
                o4[d].z *= scale; o4[d].w *= scale;
            }

            #pragma unroll
            for (int u = 0; u < 16; u++) {
                const int kk = cc * 16 + u;
                const float p = __expf(sv[u] - m);
                l += p;
                const float4* Vr = (const float4*)(Vs + kk * DHH);
                #pragma unroll
                for (int d = 0; d < 16; d++) {
                    float4 vv = Vr[d];
                    o4[d].x += p * vv.x; o4[d].y += p * vv.y;
                    o4[d].z += p * vv.z; o4[d].w += p * vv.w;
                }
            }
        }
    }

    const float inv = 1.0f / l;
    const int b = bh / HH;
    const int h = bh % HH;
    float* obase = out + (size_t)(b * SS + qi) * DD + h * DHH;
    #pragma unroll
    for (int d = 0; d < 16; d++) {
        float4 vv = o4[d];
        vv.x *= inv; vv.y *= inv; vv.z *= inv; vv.w *= inv;
        ((float4*)obase)[d] = vv;
    }
}

// ---------------------------------------------------------------------------
extern "C" void kernel_launch(void* const* d_in, const int* in_sizes, int n_in,
                              void* d_out, int out_size)
{
    const float* x    = (const float*)d_in[0];   // [B,S,D]
    const float* W    = (const float*)d_in[1];   // [D,3D]
    const float* bias = (const float*)d_in[2];   // [3D]
    float* out        = (float*)d_out;           // [B,S,D]

    cudaFuncSetAttribute(qkv_gemm_hmma, cudaFuncAttributeMaxDynamicSharedMemorySize, GEMM_SMEM);

    conv_x_kernel<<<(MTOT * KTOT) / (4 * 256), 256>>>(x);
    conv_w_kernel<<<dim3(NTOT / 32, KTOT / 32), dim3(32, 8)>>>(W);

    dim3 gemm_grid(NTOT / 128, MTOT / 128);   // (24, 64)
    qkv_gemm_hmma<<<gemm_grid, 256, GEMM_SMEM>>>(bias);

    dim3 attn_grid(SS / ATT_QROWS, BB * HH);  // (16, 64)
    attn_kernel<<<attn_grid, 128>>>(out);
}

// round 4
// speedup vs baseline: 2.4402x; 1.9772x over previous
#include <cuda_runtime.h>
#include <cuda_bf16.h>
#include <cstdint>

// Problem constants
#define BB 4
#define SS 2048
#define DD 1024
#define HH 16
#define DHH 64
#define MTOT (BB*SS)     // 8192
#define NTOT (3*DD)      // 3072
#define KTOT (DD)        // 1024
#define KP   (3*KTOT)    // 3072: expanded K -> [hi|hi|lo] x [hi|lo|hi]

#define QKVN ((size_t)BB*HH*SS*DHH)

// Scratch: GEMM inputs (bf16 split), attention operands (bf16 split)
__device__ __align__(16) __nv_bfloat16 g_A[(size_t)MTOT*KP];   // [M, K'] K-major
__device__ __align__(16) __nv_bfloat16 g_B[(size_t)NTOT*KP];   // [N, K'] K-major
__device__ __align__(16) __nv_bfloat16 g_Qh[QKVN], g_Ql[QKVN]; // [B,H,S,64] (pre-scaled 1/8)
__device__ __align__(16) __nv_bfloat16 g_Kh[QKVN], g_Kl[QKVN]; // [B,H,S,64]
__device__ __align__(16) __nv_bfloat16 g_Vh[QKVN], g_Vl[QKVN]; // [B,H,64,S]  (transposed)

// ---------------------------------------------------------------------------
// Helpers (sm_103 baseline-safe: ldmatrix / mma.sync / cp.async only)
// ---------------------------------------------------------------------------
__device__ __forceinline__ uint32_t smem_u32(const void* p) {
    uint32_t a;
    asm("{ .reg .u64 t; cvta.to.shared.u64 t, %1; cvt.u32.u64 %0, t; }" : "=r"(a) : "l"(p));
    return a;
}
__device__ __forceinline__ void ldm_x4(uint32_t* r, uint32_t addr) {
    asm volatile("ldmatrix.sync.aligned.m8n8.x4.shared.b16 {%0,%1,%2,%3}, [%4];"
        : "=r"(r[0]), "=r"(r[1]), "=r"(r[2]), "=r"(r[3]) : "r"(addr));
}
__device__ __forceinline__ void mma16816(float* d, const uint32_t* a, uint32_t b0, uint32_t b1) {
    asm volatile("mma.sync.aligned.m16n8k16.row.col.f32.bf16.bf16.f32 "
        "{%0,%1,%2,%3}, {%4,%5,%6,%7}, {%8,%9}, {%0,%1,%2,%3};"
        : "+f"(d[0]), "+f"(d[1]), "+f"(d[2]), "+f"(d[3])
        : "r"(a[0]), "r"(a[1]), "r"(a[2]), "r"(a[3]), "r"(b0), "r"(b1));
}
__device__ __forceinline__ void cp16(uint32_t dst, const void* src) {
    asm volatile("cp.async.cg.shared.global [%0], [%1], 16;" :: "r"(dst), "l"(src));
}
#define CP_COMMIT() asm volatile("cp.async.commit_group;" ::: "memory")
#define CP_WAIT1()  asm volatile("cp.async.wait_group 1;" ::: "memory")
#define CP_WAIT0()  asm volatile("cp.async.wait_group 0;" ::: "memory")

// pack two f32 -> bf16x2 reg: low half = e0, high half = e1
__device__ __forceinline__ uint32_t packbf(float e1, float e0) {
    uint32_t r; asm("cvt.rn.bf16x2.f32 %0, %1, %2;" : "=r"(r) : "f"(e1), "f"(e0)); return r;
}
// residual pack: (e - bf16(e)) for both halves
__device__ __forceinline__ uint32_t lopack(uint32_t h, float e1, float e0) {
    __nv_bfloat162 hb = *reinterpret_cast<__nv_bfloat162*>(&h);
    return packbf(e1 - __bfloat162float(hb.y), e0 - __bfloat162float(hb.x));
}
__device__ __forceinline__ void split2(float x, float y, __nv_bfloat162& hi, __nv_bfloat162& lo) {
    hi.x = __float2bfloat16(x); hi.y = __float2bfloat16(y);
    lo.x = __float2bfloat16(x - __bfloat162float(hi.x));
    lo.y = __float2bfloat16(y - __bfloat162float(hi.y));
}

// ---------------------------------------------------------------------------
// Conversion: x -> bf16 hi/lo expanded A' [M, 3K]; sectors [hi | hi | lo]
// ---------------------------------------------------------------------------
__global__ __launch_bounds__(256) void conv_x_kernel(const float* __restrict__ x)
{
    const int idx  = blockIdx.x * 256 + threadIdx.x;
    const int base = idx * 4;
    const int m = base >> 10;
    const int k = base & 1023;
    float4 v = *(const float4*)(x + base);

    __nv_bfloat162 ha, hb, la, lb;
    split2(v.x, v.y, ha, la);
    split2(v.z, v.w, hb, lb);

    __nv_bfloat16* row = g_A + (size_t)m * KP;
    *(__nv_bfloat162*)(row + k)          = ha;
    *(__nv_bfloat162*)(row + k + 2)      = hb;
    *(__nv_bfloat162*)(row + k + 1024)   = ha;
    *(__nv_bfloat162*)(row + k + 1026)   = hb;
    *(__nv_bfloat162*)(row + k + 2048)   = la;
    *(__nv_bfloat162*)(row + k + 2050)   = lb;
}

// ---------------------------------------------------------------------------
// Conversion: W [K,N] -> B' [N, 3K] bf16, sectors [hi | lo | hi] (transpose)
// ---------------------------------------------------------------------------
__global__ __launch_bounds__(256) void conv_w_kernel(const float* __restrict__ W)
{
    __shared__ float T[32][33];
    const int n0 = blockIdx.x * 32;
    const int k0 = blockIdx.y * 32;
    const int tx = threadIdx.x;   // 0..31
    const int ty = threadIdx.y;   // 0..7

    #pragma unroll
    for (int i = 0; i < 4; i++)
        T[ty + i * 8][tx] = W[(size_t)(k0 + ty + i * 8) * NTOT + n0 + tx];
    __syncthreads();

    #pragma unroll
    for (int i = 0; i < 4; i++) {
        const int n = n0 + ty + i * 8;
        const float v = T[tx][ty + i * 8];
        __nv_bfloat16 hi = __float2bfloat16(v);
        __nv_bfloat16 lo = __float2bfloat16(v - __bfloat162float(hi));
        __nv_bfloat16* row = g_B + (size_t)n * KP;
        row[k0 + tx]        = hi;
        row[k0 + tx + 1024] = lo;
        row[k0 + tx + 2048] = hi;
    }
}

// ---------------------------------------------------------------------------
// HMMA GEMM: C[8192,3072] = A' @ B'^T. CTA 128x128, BK=32, 3-stage cp.async.
// Epilogue: +bias -> split bf16 hi/lo -> Q (x1/8), K, V^T scratch.
// ---------------------------------------------------------------------------
#define ROWB 80
#define STG_BYTES (128*ROWB*2)
#define GSTG 3
#define GEMM_SMEM (GSTG*STG_BYTES)  // 61440

__device__ __forceinline__ void gemm_load_stage(uint32_t smb, int s, int kc,
                                                int m0, int n0, int tid)
{
    const int row = tid >> 1;
    const int c0  = (tid & 1) * 2;
    const __nv_bfloat16* asrc = g_A + (size_t)(m0 + row) * KP + kc + c0 * 8;
    uint32_t adst = smb + s * STG_BYTES + row * ROWB + c0 * 16;
    cp16(adst,      asrc);
    cp16(adst + 16, asrc + 8);
    const __nv_bfloat16* bsrc = g_B + (size_t)(n0 + row) * KP + kc + c0 * 8;
    uint32_t bdst = smb + s * STG_BYTES + 128 * ROWB + row * ROWB + c0 * 16;
    cp16(bdst,      bsrc);
    cp16(bdst + 16, bsrc + 8);
}

__global__ __launch_bounds__(256, 2) void qkv_gemm_hmma(const float* __restrict__ bias)
{
    extern __shared__ __align__(16) char sm[];
    const uint32_t smb = smem_u32(sm);
    const int tid = threadIdx.x, lane = tid & 31, wid = tid >> 5;
    const int m0 = blockIdx.y * 128;
    const int n0 = blockIdx.x * 128;
    const int wm = wid & 1;
    const int wn = wid >> 1;

    float acc[4][4][4];
    #pragma unroll
    for (int i = 0; i < 4; i++)
        #pragma unroll
        for (int j = 0; j < 4; j++)
            #pragma unroll
            for (int r = 0; r < 4; r++) acc[i][j][r] = 0.0f;

    gemm_load_stage(smb, 0, 0,  m0, n0, tid);
    CP_COMMIT();
    gemm_load_stage(smb, 1, 32, m0, n0, tid);
    CP_COMMIT();

    const int NIT = KP / 32;   // 96
    for (int it = 0; it < NIT; it++) {
        CP_WAIT1();
        __syncthreads();
        if (it + 2 < NIT)
            gemm_load_stage(smb, (it + 2) % GSTG, (it + 2) * 32, m0, n0, tid);
        CP_COMMIT();

        const uint32_t sb = smb + (it % GSTG) * STG_BYTES;
        #pragma unroll
        for (int ks = 0; ks < 2; ks++) {
            uint32_t a[4][4], b[2][4];
            #pragma unroll
            for (int mt = 0; mt < 4; mt++) {
                const int r = wm * 64 + mt * 16 + (lane & 15);
                ldm_x4(a[mt], sb + r * ROWB + (ks * 2 + (lane >> 4)) * 16);
            }
            #pragma unroll
            for (int bt = 0; bt < 2; bt++) {
                const int r = wn * 32 + bt * 16 + (lane & 15);
                ldm_x4(b[bt], sb + 128 * ROWB + r * ROWB + (ks * 2 + (lane >> 4)) * 16);
            }
            #pragma unroll
            for (int mt = 0; mt < 4; mt++)
                #pragma unroll
                for (int nt = 0; nt < 4; nt++) {
                    const int bt = nt >> 1, sub = nt & 1;
                    mma16816(acc[mt][nt], a[mt], b[bt][sub], b[bt][sub + 2]);
                }
        }
    }

    // Epilogue: +bias, split hi/lo, write Q/K (row-major) and V (transposed)
    #pragma unroll
    for (int mt = 0; mt < 4; mt++) {
        #pragma unroll
        for (int nt = 0; nt < 4; nt++) {
            const int m = m0 + wm * 64 + mt * 16 + (lane >> 2);
            const int n = n0 + wn * 32 + (nt >> 1) * 16 + (nt & 1) * 8 + 2 * (lane & 3);
            const float2 bb = *(const float2*)(bias + n);
            const int hh    = n / 192;
            const int which = (n >> 6) % 3;
            const int dh    = n & 63;
            const int bi = m >> 11, si = m & 2047;
            const int bh = bi * HH + hh;
            #pragma unroll
            for (int rr = 0; rr < 2; rr++) {
                const int s = si + rr * 8;
                float vx = acc[mt][nt][rr * 2 + 0] + bb.x;
                float vy = acc[mt][nt][rr * 2 + 1] + bb.y;
                if (which == 0) { vx *= 0.125f; vy *= 0.125f; }
                __nv_bfloat162 hi, lo;
                split2(vx, vy, hi, lo);
                if (which == 2) {
                    const size_t vb = ((size_t)bh * DHH + dh) * SS + s;
                    g_Vh[vb]      = hi.x;  g_Vh[vb + SS] = hi.y;
                    g_Vl[vb]      = lo.x;  g_Vl[vb + SS] = lo.y;
                } else {
                    const size_t qb = ((size_t)bh * SS + s) * DHH + dh;
                    __nv_bfloat16* dh_ = (which == 0) ? g_Qh : g_Kh;
                    __nv_bfloat16* dl_ = (which == 0) ? g_Ql : g_Kl;
                    *(__nv_bfloat162*)(dh_ + qb) = hi;
                    *(__nv_bfloat162*)(dl_ + qb) = lo;
                }
            }
        }
    }
}

// ---------------------------------------------------------------------------
// HMMA causal flash attention.
// CTA: 128 q rows, 4 warps x 32 rows. K-tiles of 64 keys, double-buffered.
// QK = QhKh + QlKh + QhKl; PV = PhVh + PlVh + PhVl (bf16 hi/lo splits).
// ---------------------------------------------------------------------------
#define APITCH 144
#define AST 36864   // stage bytes: Kh@0 Kl@9216 Vh@18432 Vl@27648 (64 rows x 144B)
#define ATT_SMEM (2*AST)  // 73728

__global__ __launch_bounds__(128) void attn_hmma(float* __restrict__ out)
{
    extern __shared__ __align__(16) char sm[];
    const uint32_t smb = smem_u32(sm);
    const int tid = threadIdx.x, lane = tid & 31, w = tid >> 5;
    const int bh = blockIdx.y, qt = blockIdx.x;
    const int q0 = qt * 128;
    const int tg = lane & 3, g = lane >> 2;

    // --- stage Q tile (hi @0, lo @18432), then ldmatrix into regs ---
    {
        const __nv_bfloat16* qhg = g_Qh + ((size_t)bh * SS + q0) * DHH;
        const __nv_bfloat16* qlg = g_Ql + ((size_t)bh * SS + q0) * DHH;
        #pragma unroll
        for (int i = 0; i < 8; i++) {
            const int idx = i * 128 + tid;
            const int row = idx >> 3, c = idx & 7;
            *(float4*)(sm + row * APITCH + c * 16)         = *(const float4*)(qhg + row * 64 + c * 8);
            *(float4*)(sm + 18432 + row * APITCH + c * 16) = *(const float4*)(qlg + row * 64 + c * 8);
        }
    }
    __syncthreads();
    uint32_t qh[2][4][4], qlr[2][4][4];
    #pragma unroll
    for (int mt = 0; mt < 2; mt++)
        #pragma unroll
        for (int kc = 0; kc < 4; kc++) {
            const uint32_t ad = smb + (w * 32 + mt * 16 + (lane & 15)) * APITCH
                              + (kc * 2 + (lane >> 4)) * 16;
            ldm_x4(qh[mt][kc], ad);
            ldm_x4(qlr[mt][kc], ad + 18432);
        }
    __syncthreads();

    float o[2][8][4];
    #pragma unroll
    for (int mt = 0; mt < 2; mt++)
        #pragma unroll
        for (int nt = 0; nt < 8; nt++)
            #pragma unroll
            for (int e = 0; e < 4; e++) o[mt][nt][e] = 0.0f;
    float mrow[2][2] = {{-1e30f, -1e30f}, {-1e30f, -1e30f}};
    float lrow[2][2] = {{0.f, 0.f}, {0.f, 0.f}};

    const __nv_bfloat16* khb = g_Kh + (size_t)bh * SS * DHH;
    const __nv_bfloat16* klb = g_Kl + (size_t)bh * SS * DHH;
    const __nv_bfloat16* vhb = g_Vh + (size_t)bh * DHH * SS;
    const __nv_bfloat16* vlb = g_Vl + (size_t)bh * DHH * SS;

    const int nkt = qt * 2 + 2;

    // preload tile 0
    {
        const uint32_t base = smb;
        #pragma unroll
        for (int i = 0; i < 4; i++) {
            const int idx = i * 128 + tid;
            const int row = idx >> 3, c = idx & 7;
            cp16(base + row * APITCH + c * 16,         khb + row * 64 + c * 8);
            cp16(base + 9216 + row * APITCH + c * 16,  klb + row * 64 + c * 8);
            cp16(base + 18432 + row * APITCH + c * 16, vhb + (size_t)row * SS + c * 8);
            cp16(base + 27648 + row * APITCH + c * 16, vlb + (size_t)row * SS + c * 8);
        }
    }
    CP_COMMIT();

    #pragma unroll 1
    for (int jt = 0; jt < nkt; jt++) {
        CP_WAIT0();
        __syncthreads();
        if (jt + 1 < nkt) {
            const uint32_t base = smb + ((jt + 1) & 1) * AST;
            const int j1 = (jt + 1) * 64;
            #pragma unroll
            for (int i = 0; i < 4; i++) {
                const int idx = i * 128 + tid;
                const int row = idx >> 3, c = idx & 7;
                cp16(base + row * APITCH + c * 16,         khb + (size_t)(j1 + row) * 64 + c * 8);
                cp16(base + 9216 + row * APITCH + c * 16,  klb + (size_t)(j1 + row) * 64 + c * 8);
                cp16(base + 18432 + row * APITCH + c * 16, vhb + (size_t)row * SS + j1 + c * 8);
                cp16(base + 27648 + row * APITCH + c * 16, vlb + (size_t)row * SS + j1 + c * 8);
            }
        }
        CP_COMMIT();

        const uint32_t kb = smb + (jt & 1) * AST;
        const int j0 = jt * 64;

        // ---- S = Q K^T (3 split terms) ----
        float s2[2][8][4];
        #pragma unroll
        for (int mt = 0; mt < 2; mt++)
            #pragma unroll
            for (int nt = 0; nt < 8; nt++)
                #pragma unroll
                for (int e = 0; e < 4; e++) s2[mt][nt][e] = 0.0f;

        #pragma unroll
        for (int term = 0; term < 3; term++) {
            const uint32_t boff = kb + (term == 2 ? 9216 : 0);
            #pragma unroll
            for (int kc = 0; kc < 4; kc++) {
                uint32_t b[4][4];
                #pragma unroll
                for (int bt = 0; bt < 4; bt++)
                    ldm_x4(b[bt], boff + (bt * 16 + (lane & 15)) * APITCH
                                 + (kc * 2 + (lane >> 4)) * 16);
                #pragma unroll
                for (int mt = 0; mt < 2; mt++) {
                    const uint32_t* a = (term == 1) ? qlr[mt][kc] : qh[mt][kc];
                    #pragma unroll
                    for (int nt = 0; nt < 8; nt++)
                        mma16816(s2[mt][nt], a, b[nt >> 1][nt & 1], b[nt >> 1][(nt & 1) + 2]);
                }
            }
        }

        // ---- mask + online softmax ----
        const bool need_mask = (j0 + 63 > q0 + w * 32);
        #pragma unroll
        for (int mt = 0; mt < 2; mt++) {
            #pragma unroll
            for (int rs = 0; rs < 2; rs++) {
                const int row = q0 + w * 32 + mt * 16 + g + rs * 8;
                if (need_mask) {
                    #pragma unroll
                    for (int nt = 0; nt < 8; nt++)
                        #pragma unroll
                        for (int e = 0; e < 2; e++) {
                            const int key = j0 + nt * 8 + tg * 2 + e;
                            if (key > row) s2[mt][nt][rs * 2 + e] = -1e30f;
                        }
                }
                float mx = -1e30f;
                #pragma unroll
                for (int nt = 0; nt < 8; nt++)
                    mx = fmaxf(mx, fmaxf(s2[mt][nt][rs * 2], s2[mt][nt][rs * 2 + 1]));
                mx = fmaxf(mx, __shfl_xor_sync(0xffffffffu, mx, 1));
                mx = fmaxf(mx, __shfl_xor_sync(0xffffffffu, mx, 2));
                const float mn = fmaxf(mrow[mt][rs], mx);
                const float sc = __expf(mrow[mt][rs] - mn);
                mrow[mt][rs] = mn;
                float ps = 0.0f;
                #pragma unroll
                for (int nt = 0; nt < 8; nt++) {
                    float p0 = __expf(s2[mt][nt][rs * 2]     - mn);
                    float p1 = __expf(s2[mt][nt][rs * 2 + 1] - mn);
                    s2[mt][nt][rs * 2] = p0; s2[mt][nt][rs * 2 + 1] = p1;
                    ps += p0 + p1;
                    o[mt][nt][rs * 2] *= sc; o[mt][nt][rs * 2 + 1] *= sc;
                }
                lrow[mt][rs] = lrow[mt][rs] * sc + ps;
            }
        }

        // ---- O += P V (3 split terms); A frags packed from s2 registers ----
        #pragma unroll
        for (int term = 0; term < 3; term++) {
            const uint32_t boff = kb + (term == 2 ? 27648 : 18432);
            #pragma unroll
            for (int kc = 0; kc < 4; kc++) {
                uint32_t b[4][4];
                #pragma unroll
                for (int bt = 0; bt < 4; bt++)
                    ldm_x4(b[bt], boff + (bt * 16 + (lane & 15)) * APITCH
                                 + (kc * 2 + (lane >> 4)) * 16);
                #pragma unroll
                for (int mt = 0; mt < 2; mt++) {
                    uint32_t a[4];
                    const uint32_t h0 = packbf(s2[mt][2*kc][1],   s2[mt][2*kc][0]);
                    const uint32_t h1 = packbf(s2[mt][2*kc][3],   s2[mt][2*kc][2]);
                    const uint32_t h2 = packbf(s2[mt][2*kc+1][1], s2[mt][2*kc+1][0]);
                    const uint32_t h3 = packbf(s2[mt][2*kc+1][3], s2[mt][2*kc+1][2]);
                    if (term != 1) { a[0] = h0; a[1] = h1; a[2] = h2; a[3] = h3; }
                    else {
                        a[0] = lopack(h0, s2[mt][2*kc][1],   s2[mt][2*kc][0]);
                        a[1] = lopack(h1, s2[mt][2*kc][3],   s2[mt][2*kc][2]);
                        a[2] = lopack(h2, s2[mt][2*kc+1][1], s2[mt][2*kc+1][0]);
                        a[3] = lopack(h3, s2[mt][2*kc+1][3], s2[mt][2*kc+1][2]);
                    }
                    #pragma unroll
                    for (int nt = 0; nt < 8; nt++)
                        mma16816(o[mt][nt], a, b[nt >> 1][nt & 1], b[nt >> 1][(nt & 1) + 2]);
                }
            }
        }
    }

    // ---- finalize: normalize, write out[b, s, h*64+dh] ----
    const int b = bh >> 4, h = bh & 15;
    #pragma unroll
    for (int mt = 0; mt < 2; mt++) {
        float l0 = lrow[mt][0];
        l0 += __shfl_xor_sync(0xffffffffu, l0, 1);
        l0 += __shfl_xor_sync(0xffffffffu, l0, 2);
        float l1 = lrow[mt][1];
        l1 += __shfl_xor_sync(0xffffffffu, l1, 1);
        l1 += __shfl_xor_sync(0xffffffffu, l1, 2);
        const float i0 = 1.0f / l0, i1 = 1.0f / l1;
        const int row = q0 + w * 32 + mt * 16 + g;
        #pragma unroll
        for (int nt = 0; nt < 8; nt++) {
            const int col = h * 64 + nt * 8 + tg * 2;
            float2 v0 = make_float2(o[mt][nt][0] * i0, o[mt][nt][1] * i0);
            *(float2*)(out + ((size_t)(b * SS + row)) * DD + col) = v0;
            float2 v1 = make_float2(o[mt][nt][2] * i1, o[mt][nt][3] * i1);
            *(float2*)(out + ((size_t)(b * SS + row + 8)) * DD + col) = v1;
        }
    }
}

// ---------------------------------------------------------------------------
extern "C" void kernel_launch(void* const* d_in, const int* in_sizes, int n_in,
                              void* d_out, int out_size)
{
    const float* x    = (const float*)d_in[0];   // [B,S,D]
    const float* W    = (const float*)d_in[1];   // [D,3D]
    const float* bias = (const float*)d_in[2];   // [3D]
    float* out        = (float*)d_out;           // [B,S,D]

    cudaFuncSetAttribute(qkv_gemm_hmma, cudaFuncAttributeMaxDynamicSharedMemorySize, GEMM_SMEM);
    cudaFuncSetAttribute(attn_hmma,     cudaFuncAttributeMaxDynamicSharedMemorySize, ATT_SMEM);

    conv_x_kernel<<<(MTOT * KTOT) / (4 * 256), 256>>>(x);
    conv_w_kernel<<<dim3(NTOT / 32, KTOT / 32), dim3(32, 8)>>>(W);

    dim3 gemm_grid(NTOT / 128, MTOT / 128);   // (24, 64)
    qkv_gemm_hmma<<<gemm_grid, 256, GEMM_SMEM>>>(bias);

    dim3 attn_grid(SS / 128, BB * HH);        // (16, 64)
    attn_hmma<<<attn_grid, 128, ATT_SMEM>>>(out);
}

// round 5
// speedup vs baseline: 6.9449x; 2.8461x over previous
#include <cuda_runtime.h>
#include <cuda_fp16.h>
#include <cstdint>

// Problem constants
#define BB 4
#define SS 2048
#define DD 1024
#define HH 16
#define DHH 64
#define MTOT (BB*SS)     // 8192
#define NTOT (3*DD)      // 3072
#define KTOT (DD)        // 1024

#define QKVN ((size_t)BB*HH*SS*DHH)

// Scratch: fp16 single-precision-pass operands
__device__ __align__(16) __half g_A[(size_t)MTOT*KTOT];   // x   [M, K] K-major
__device__ __align__(16) __half g_B[(size_t)NTOT*KTOT];   // W^T [N, K] K-major
__device__ __align__(16) __half g_Qh[QKVN];               // [B,H,S,64] (pre-scaled 1/8)
__device__ __align__(16) __half g_Kh[QKVN];               // [B,H,S,64]
__device__ __align__(16) __half g_Vh[QKVN];               // [B,H,64,S] (transposed)

// ---------------------------------------------------------------------------
// Helpers (sm_103 baseline-safe: ldmatrix / mma.sync / cp.async only)
// ---------------------------------------------------------------------------
__device__ __forceinline__ uint32_t smem_u32(const void* p) {
    uint32_t a;
    asm("{ .reg .u64 t; cvta.to.shared.u64 t, %1; cvt.u32.u64 %0, t; }" : "=r"(a) : "l"(p));
    return a;
}
__device__ __forceinline__ void ldm_x4(uint32_t* r, uint32_t addr) {
    asm volatile("ldmatrix.sync.aligned.m8n8.x4.shared.b16 {%0,%1,%2,%3}, [%4];"
        : "=r"(r[0]), "=r"(r[1]), "=r"(r[2]), "=r"(r[3]) : "r"(addr));
}
__device__ __forceinline__ void mma16816(float* d, const uint32_t* a, uint32_t b0, uint32_t b1) {
    asm volatile("mma.sync.aligned.m16n8k16.row.col.f32.f16.f16.f32 "
        "{%0,%1,%2,%3}, {%4,%5,%6,%7}, {%8,%9}, {%0,%1,%2,%3};"
        : "+f"(d[0]), "+f"(d[1]), "+f"(d[2]), "+f"(d[3])
        : "r"(a[0]), "r"(a[1]), "r"(a[2]), "r"(a[3]), "r"(b0), "r"(b1));
}
__device__ __forceinline__ void cp16(uint32_t dst, const void* src) {
    asm volatile("cp.async.cg.shared.global [%0], [%1], 16;" :: "r"(dst), "l"(src));
}
#define CP_COMMIT() asm volatile("cp.async.commit_group;" ::: "memory")
#define CP_WAIT1()  asm volatile("cp.async.wait_group 1;" ::: "memory")
#define CP_WAIT0()  asm volatile("cp.async.wait_group 0;" ::: "memory")

// pack two f32 -> f16x2 reg: low half = e0, high half = e1
__device__ __forceinline__ uint32_t packhf(float e1, float e0) {
    uint32_t r; asm("cvt.rn.f16x2.f32 %0, %1, %2;" : "=r"(r) : "f"(e1), "f"(e0)); return r;
}

// ---------------------------------------------------------------------------
// Conversion: x [M,K] fp32 -> g_A fp16
// ---------------------------------------------------------------------------
__global__ __launch_bounds__(256) void conv_x_kernel(const float* __restrict__ x)
{
    const int idx  = blockIdx.x * 256 + threadIdx.x;
    const int base = idx * 4;
    float4 v = *(const float4*)(x + base);
    __half2 a; a.x = __float2half(v.x); a.y = __float2half(v.y);
    __half2 b; b.x = __float2half(v.z); b.y = __float2half(v.w);
    *(__half2*)(g_A + base)     = a;
    *(__half2*)(g_A + base + 2) = b;
}

// ---------------------------------------------------------------------------
// Conversion: W [K,N] fp32 -> g_B [N,K] fp16 (transpose)
// ---------------------------------------------------------------------------
__global__ __launch_bounds__(256) void conv_w_kernel(const float* __restrict__ W)
{
    __shared__ float T[32][33];
    const int n0 = blockIdx.x * 32;
    const int k0 = blockIdx.y * 32;
    const int tx = threadIdx.x;   // 0..31
    const int ty = threadIdx.y;   // 0..7

    #pragma unroll
    for (int i = 0; i < 4; i++)
        T[ty + i * 8][tx] = W[(size_t)(k0 + ty + i * 8) * NTOT + n0 + tx];
    __syncthreads();

    #pragma unroll
    for (int i = 0; i < 4; i++) {
        const int n = n0 + ty + i * 8;
        g_B[(size_t)n * KTOT + k0 + tx] = __float2half(T[tx][ty + i * 8]);
    }
}

// ---------------------------------------------------------------------------
// HMMA GEMM (fp16 single pass): C[8192,3072] = A @ B^T.
// CTA 128x128, BK=32, 3-stage cp.async. Epilogue: +bias -> fp16 Q(x1/8)/K/V^T.
// ---------------------------------------------------------------------------
#define ROWB 80
#define STG_BYTES (128*ROWB*2)
#define GSTG 3
#define GEMM_SMEM (GSTG*STG_BYTES)  // 61440

__device__ __forceinline__ void gemm_load_stage(uint32_t smb, int s, int kc,
                                                int m0, int n0, int tid)
{
    const int row = tid >> 1;
    const int c0  = (tid & 1) * 2;
    const __half* asrc = g_A + (size_t)(m0 + row) * KTOT + kc + c0 * 8;
    uint32_t adst = smb + s * STG_BYTES + row * ROWB + c0 * 16;
    cp16(adst,      asrc);
    cp16(adst + 16, asrc + 8);
    const __half* bsrc = g_B + (size_t)(n0 + row) * KTOT + kc + c0 * 8;
    uint32_t bdst = smb + s * STG_BYTES + 128 * ROWB + row * ROWB + c0 * 16;
    cp16(bdst,      bsrc);
    cp16(bdst + 16, bsrc + 8);
}

__global__ __launch_bounds__(256, 2) void qkv_gemm_hmma(const float* __restrict__ bias)
{
    extern __shared__ __align__(16) char sm[];
    const uint32_t smb = smem_u32(sm);
    const int tid = threadIdx.x, lane = tid & 31, wid = tid >> 5;
    const int m0 = blockIdx.y * 128;
    const int n0 = blockIdx.x * 128;
    const int wm = wid & 1;
    const int wn = wid >> 1;

    float acc[4][4][4];
    #pragma unroll
    for (int i = 0; i < 4; i++)
        #pragma unroll
        for (int j = 0; j < 4; j++)
            #pragma unroll
            for (int r = 0; r < 4; r++) acc[i][j][r] = 0.0f;

    gemm_load_stage(smb, 0, 0,  m0, n0, tid);
    CP_COMMIT();
    gemm_load_stage(smb, 1, 32, m0, n0, tid);
    CP_COMMIT();

    const int NIT = KTOT / 32;   // 32
    for (int it = 0; it < NIT; it++) {
        CP_WAIT1();
        __syncthreads();
        if (it + 2 < NIT)
            gemm_load_stage(smb, (it + 2) % GSTG, (it + 2) * 32, m0, n0, tid);
        CP_COMMIT();

        const uint32_t sb = smb + (it % GSTG) * STG_BYTES;
        #pragma unroll
        for (int ks = 0; ks < 2; ks++) {
            uint32_t a[4][4], b[2][4];
            #pragma unroll
            for (int mt = 0; mt < 4; mt++) {
                const int r = wm * 64 + mt * 16 + (lane & 15);
                ldm_x4(a[mt], sb + r * ROWB + (ks * 2 + (lane >> 4)) * 16);
            }
            #pragma unroll
            for (int bt = 0; bt < 2; bt++) {
                const int r = wn * 32 + bt * 16 + (lane & 15);
                ldm_x4(b[bt], sb + 128 * ROWB + r * ROWB + (ks * 2 + (lane >> 4)) * 16);
            }
            #pragma unroll
            for (int mt = 0; mt < 4; mt++)
                #pragma unroll
                for (int nt = 0; nt < 4; nt++) {
                    const int bt = nt >> 1, sub = nt & 1;
                    mma16816(acc[mt][nt], a[mt], b[bt][sub], b[bt][sub + 2]);
                }
        }
    }

    // Epilogue: +bias, fp16, write Q (x1/8) / K (row-major) and V (transposed)
    #pragma unroll
    for (int mt = 0; mt < 4; mt++) {
        #pragma unroll
        for (int nt = 0; nt < 4; nt++) {
            const int m = m0 + wm * 64 + mt * 16 + (lane >> 2);
            const int n = n0 + wn * 32 + (nt >> 1) * 16 + (nt & 1) * 8 + 2 * (lane & 3);
            const float2 bb = *(const float2*)(bias + n);
            const int hh    = n / 192;
            const int which = (n >> 6) % 3;
            const int dh    = n & 63;
            const int bi = m >> 11, si = m & 2047;
            const int bh = bi * HH + hh;
            #pragma unroll
            for (int rr = 0; rr < 2; rr++) {
                const int s = si + rr * 8;
                float vx = acc[mt][nt][rr * 2 + 0] + bb.x;
                float vy = acc[mt][nt][rr * 2 + 1] + bb.y;
                if (which == 0) { vx *= 0.125f; vy *= 0.125f; }
                if (which == 2) {
                    const size_t vb = ((size_t)bh * DHH + dh) * SS + s;
                    g_Vh[vb]      = __float2half(vx);
                    g_Vh[vb + SS] = __float2half(vy);
                } else {
                    const size_t qb = ((size_t)bh * SS + s) * DHH + dh;
                    __half2 hv; hv.x = __float2half(vx); hv.y = __float2half(vy);
                    *(__half2*)(((which == 0) ? g_Qh : g_Kh) + qb) = hv;
                }
            }
        }
    }
}

// ---------------------------------------------------------------------------
// HMMA causal flash attention, fp16 single pass.
// CTA: 128 q rows, 4 warps x 32 rows. K-tiles of 64 keys, double-buffered.
// ---------------------------------------------------------------------------
#define APITCH 144
#define AST 18432   // stage bytes: Kh@0, Vh@9216 (64 rows x 144B)
#define ATT_SMEM (2*AST)  // 36864

__global__ __launch_bounds__(128) void attn_hmma(float* __restrict__ out)
{
    extern __shared__ __align__(16) char sm[];
    const uint32_t smb = smem_u32(sm);
    const int tid = threadIdx.x, lane = tid & 31, w = tid >> 5;
    const int bh = blockIdx.y, qt = blockIdx.x;
    const int q0 = qt * 128;
    const int tg = lane & 3, g = lane >> 2;

    // --- stage Q tile, then ldmatrix into regs ---
    {
        const __half* qhg = g_Qh + ((size_t)bh * SS + q0) * DHH;
        #pragma unroll
        for (int i = 0; i < 8; i++) {
            const int idx = i * 128 + tid;
            const int row = idx >> 3, c = idx & 7;
            *(float4*)(sm + row * APITCH + c * 16) = *(const float4*)(qhg + row * 64 + c * 8);
        }
    }
    __syncthreads();
    uint32_t qh[2][4][4];
    #pragma unroll
    for (int mt = 0; mt < 2; mt++)
        #pragma unroll
        for (int kc = 0; kc < 4; kc++)
            ldm_x4(qh[mt][kc], smb + (w * 32 + mt * 16 + (lane & 15)) * APITCH
                              + (kc * 2 + (lane >> 4)) * 16);
    __syncthreads();

    float o[2][8][4];
    #pragma unroll
    for (int mt = 0; mt < 2; mt++)
        #pragma unroll
        for (int nt = 0; nt < 8; nt++)
            #pragma unroll
            for (int e = 0; e < 4; e++) o[mt][nt][e] = 0.0f;
    float mrow[2][2] = {{-1e30f, -1e30f}, {-1e30f, -1e30f}};
    float lrow[2][2] = {{0.f, 0.f}, {0.f, 0.f}};

    const __half* khb = g_Kh + (size_t)bh * SS * DHH;
    const __half* vhb = g_Vh + (size_t)bh * DHH * SS;

    const int nkt = qt * 2 + 2;

    // preload tile 0
    #pragma unroll
    for (int i = 0; i < 4; i++) {
        const int idx = i * 128 + tid;
        const int row = idx >> 3, c = idx & 7;
        cp16(smb + row * APITCH + c * 16,        khb + row * 64 + c * 8);
        cp16(smb + 9216 + row * APITCH + c * 16, vhb + (size_t)row * SS + c * 8);
    }
    CP_COMMIT();

    #pragma unroll 1
    for (int jt = 0; jt < nkt; jt++) {
        CP_WAIT0();
        __syncthreads();
        if (jt + 1 < nkt) {
            const uint32_t base = smb + ((jt + 1) & 1) * AST;
            const int j1 = (jt + 1) * 64;
            #pragma unroll
            for (int i = 0; i < 4; i++) {
                const int idx = i * 128 + tid;
                const int row = idx >> 3, c = idx & 7;
                cp16(base + row * APITCH + c * 16,        khb + (size_t)(j1 + row) * 64 + c * 8);
                cp16(base + 9216 + row * APITCH + c * 16, vhb + (size_t)row * SS + j1 + c * 8);
            }
        }
        CP_COMMIT();

        const uint32_t kb = smb + (jt & 1) * AST;
        const int j0 = jt * 64;

        // ---- S = Q K^T ----
        float s2[2][8][4];
        #pragma unroll
        for (int mt = 0; mt < 2; mt++)
            #pragma unroll
            for (int nt = 0; nt < 8; nt++)
                #pragma unroll
                for (int e = 0; e < 4; e++) s2[mt][nt][e] = 0.0f;

        #pragma unroll
        for (int kc = 0; kc < 4; kc++) {
            uint32_t b[4][4];
            #pragma unroll
            for (int bt = 0; bt < 4; bt++)
                ldm_x4(b[bt], kb + (bt * 16 + (lane & 15)) * APITCH
                             + (kc * 2 + (lane >> 4)) * 16);
            #pragma unroll
            for (int mt = 0; mt < 2; mt++)
                #pragma unroll
                for (int nt = 0; nt < 8; nt++)
                    mma16816(s2[mt][nt], qh[mt][kc], b[nt >> 1][nt & 1], b[nt >> 1][(nt & 1) + 2]);
        }

        // ---- mask + online softmax ----
        const bool need_mask = (j0 + 63 > q0 + w * 32);
        #pragma unroll
        for (int mt = 0; mt < 2; mt++) {
            #pragma unroll
            for (int rs = 0; rs < 2; rs++) {
                const int row = q0 + w * 32 + mt * 16 + g + rs * 8;
                if (need_mask) {
                    #pragma unroll
                    for (int nt = 0; nt < 8; nt++)
                        #pragma unroll
                        for (int e = 0; e < 2; e++) {
                            const int key = j0 + nt * 8 + tg * 2 + e;
                            if (key > row) s2[mt][nt][rs * 2 + e] = -1e30f;
                        }
                }
                float mx = -1e30f;
                #pragma unroll
                for (int nt = 0; nt < 8; nt++)
                    mx = fmaxf(mx, fmaxf(s2[mt][nt][rs * 2], s2[mt][nt][rs * 2 + 1]));
                mx = fmaxf(mx, __shfl_xor_sync(0xffffffffu, mx, 1));
                mx = fmaxf(mx, __shfl_xor_sync(0xffffffffu, mx, 2));
                const float mn = fmaxf(mrow[mt][rs], mx);
                const float sc = __expf(mrow[mt][rs] - mn);
                mrow[mt][rs] = mn;
                float ps = 0.0f;
                #pragma unroll
                for (int nt = 0; nt < 8; nt++) {
                    float p0 = __expf(s2[mt][nt][rs * 2]     - mn);
                    float p1 = __expf(s2[mt][nt][rs * 2 + 1] - mn);
                    s2[mt][nt][rs * 2] = p0; s2[mt][nt][rs * 2 + 1] = p1;
                    ps += p0 + p1;
                    o[mt][nt][rs * 2] *= sc; o[mt][nt][rs * 2 + 1] *= sc;
                }
                lrow[mt][rs] = lrow[mt][rs] * sc + ps;
            }
        }

        // ---- O += P V ----
        #pragma unroll
        for (int kc = 0; kc < 4; kc++) {
            uint32_t b[4][4];
            #pragma unroll
            for (int bt = 0; bt < 4; bt++)
                ldm_x4(b[bt], kb + 9216 + (bt * 16 + (lane & 15)) * APITCH
                             + (kc * 2 + (lane >> 4)) * 16);
            #pragma unroll
            for (int mt = 0; mt < 2; mt++) {
                uint32_t a[4];
                a[0] = packhf(s2[mt][2*kc][1],   s2[mt][2*kc][0]);
                a[1] = packhf(s2[mt][2*kc][3],   s2[mt][2*kc][2]);
                a[2] = packhf(s2[mt][2*kc+1][1], s2[mt][2*kc+1][0]);
                a[3] = packhf(s2[mt][2*kc+1][3], s2[mt][2*kc+1][2]);
                #pragma unroll
                for (int nt = 0; nt < 8; nt++)
                    mma16816(o[mt][nt], a, b[nt >> 1][nt & 1], b[nt >> 1][(nt & 1) + 2]);
            }
        }
    }

    // ---- finalize: normalize, write out[b, s, h*64+dh] ----
    const int b = bh >> 4, h = bh & 15;
    #pragma unroll
    for (int mt = 0; mt < 2; mt++) {
        float l0 = lrow[mt][0];
        l0 += __shfl_xor_sync(0xffffffffu, l0, 1);
        l0 += __shfl_xor_sync(0xffffffffu, l0, 2);
        float l1 = lrow[mt][1];
        l1 += __shfl_xor_sync(0xffffffffu, l1, 1);
        l1 += __shfl_xor_sync(0xffffffffu, l1, 2);
        const float i0 = 1.0f / l0, i1 = 1.0f / l1;
        const int row = q0 + w * 32 + mt * 16 + g;
        #pragma unroll
        for (int nt = 0; nt < 8; nt++) {
            const int col = h * 64 + nt * 8 + tg * 2;
            float2 v0 = make_float2(o[mt][nt][0] * i0, o[mt][nt][1] * i0);
            *(float2*)(out + ((size_t)(b * SS + row)) * DD + col) = v0;
            float2 v1 = make_float2(o[mt][nt][2] * i1, o[mt][nt][3] * i1);
            *(float2*)(out + ((size_t)(b * SS + row + 8)) * DD + col) = v1;
        }
    }
}

// ---------------------------------------------------------------------------
extern "C" void kernel_launch(void* const* d_in, const int* in_sizes, int n_in,
                              void* d_out, int out_size)
{
    const float* x    = (const float*)d_in[0];   // [B,S,D]
    const float* W    = (const float*)d_in[1];   // [D,3D]
    const float* bias = (const float*)d_in[2];   // [3D]
    float* out        = (float*)d_out;           // [B,S,D]

    cudaFuncSetAttribute(qkv_gemm_hmma, cudaFuncAttributeMaxDynamicSharedMemorySize, GEMM_SMEM);
    cudaFuncSetAttribute(attn_hmma,     cudaFuncAttributeMaxDynamicSharedMemorySize, ATT_SMEM);

    conv_x_kernel<<<(MTOT * KTOT) / (4 * 256), 256>>>(x);
    conv_w_kernel<<<dim3(NTOT / 32, KTOT / 32), dim3(32, 8)>>>(W);

    dim3 gemm_grid(NTOT / 128, MTOT / 128);   // (24, 64)
    qkv_gemm_hmma<<<gemm_grid, 256, GEMM_SMEM>>>(bias);

    dim3 attn_grid(SS / 128, BB * HH);        // (16, 64)
    attn_hmma<<<attn_grid, 128, ATT_SMEM>>>(out);
}